// round 16
// baseline (speedup 1.0000x reference)
#include <cuda_runtime.h>
#include <cuda_bf16.h>
#include <cstdint>
#include <math.h>

// Problem constants
#define BB 8192
#define P3 24
#define E_PER 90
#define EDGE_DIM 16
#define NROWS 196608   // B * 24

// Output layout (float32 concat of the 4 reference outputs)
#define OFF_NODE 0
#define OFF_EI 50331648
#define EI_HALF 737280
#define OFF_EA 51806208
#define OFF_BV 63602688

// ---------------------------------------------------------------------------
// Pre-generated B fragments for mma.m16n8k16 (bf16).
// Index: [c (16-col group, 0..15)][ks (0..15)][lane (0..31)] -> uint4
// ---------------------------------------------------------------------------
__device__ __align__(16) uint4 g_Wfrag[16 * 16 * 32];   // 128 KB

__device__ __forceinline__ uint32_t smem_u32(const void* p) {
    uint32_t a;
    asm("{ .reg .u64 t; cvta.to.shared.u64 t, %1; cvt.u32.u64 %0, t; }"
        : "=r"(a) : "l"(p));
    return a;
}

__device__ __forceinline__ void stcs4(float4* p, float4 v) {
    asm volatile("st.global.cs.v4.f32 [%0], {%1,%2,%3,%4};"
                 :: "l"(p), "f"(v.x), "f"(v.y), "f"(v.z), "f"(v.w) : "memory");
}

#define LDSM_X4(r0, r1, r2, r3, addr) \
    asm volatile("ldmatrix.sync.aligned.m8n8.x4.shared.b16 {%0,%1,%2,%3}, [%4];" \
        : "=r"(r0), "=r"(r1), "=r"(r2), "=r"(r3) : "r"(addr))

__device__ __forceinline__ void mma16816(float* d, uint32_t a0, uint32_t a1,
                                         uint32_t a2, uint32_t a3,
                                         uint32_t b0, uint32_t b1) {
    asm volatile(
        "mma.sync.aligned.m16n8k16.row.col.f32.bf16.bf16.f32 "
        "{%0,%1,%2,%3}, {%4,%5,%6,%7}, {%8,%9}, {%0,%1,%2,%3};"
        : "+f"(d[0]), "+f"(d[1]), "+f"(d[2]), "+f"(d[3])
        : "r"(a0), "r"(a1), "r"(a2), "r"(a3), "r"(b0), "r"(b1));
}

// ---------------------------------------------------------------------------
// prep: build g_Wfrag from Wq/Wk (f32)
// ---------------------------------------------------------------------------
__device__ __forceinline__ uint32_t pack_w(const float* __restrict__ Wq,
                                           const float* __restrict__ Wk,
                                           int n, int k) {
    const float* Wr = (n < 128) ? (Wq + (size_t)n * 256)
                                : (Wk + (size_t)(n - 128) * 256);
    __nv_bfloat162 h = __float22bfloat162_rn(make_float2(Wr[k], Wr[k + 1]));
    return *reinterpret_cast<uint32_t*>(&h);
}

__global__ void __launch_bounds__(256)
prep_kernel(const float* __restrict__ Wq, const float* __restrict__ Wk)
{
    int idx = blockIdx.x * 256 + threadIdx.x;     // 0..8191
    int c = idx >> 9, ks = (idx >> 5) & 15, l = idx & 31;
    int n0 = c * 16 + (l >> 2);
    int k0 = ks * 16 + (l & 3) * 2;
    uint4 u;
    u.x = pack_w(Wq, Wk, n0,     k0);
    u.y = pack_w(Wq, Wk, n0,     k0 + 8);
    u.z = pack_w(Wq, Wk, n0 + 8, k0);
    u.w = pack_w(Wq, Wk, n0 + 8, k0 + 8);
    g_Wfrag[idx] = u;
}

// ---------------------------------------------------------------------------
// fused kernel: 1 sample (24 rows) per block, 128 threads, 8 CTAs/SM.
// Warps 0-1: q rows (m-base 0),  cols [64w, 64w+64).
// Warps 2-3: k rows (m-base 8),  cols [64w, 64w+64).
// One m-tile per warp per k-step -> LDSM traffic halved vs 2-sample tiling.
// Y (24x512B) overlays A. smem total: 12288 B -> 8 CTAs/SM, L1D ~130KB
// keeps the 128KB Wfrag stream L1-resident.
// ---------------------------------------------------------------------------
#define FS_TOTAL 12288

__global__ void __launch_bounds__(128, 8)
fused_kernel(const float4* __restrict__ text, const float4* __restrict__ audio,
             const float4* __restrict__ facial,
             const float* __restrict__ bq, const float* __restrict__ bk,
             const float* __restrict__ emb, float* __restrict__ out)
{
    extern __shared__ char smc[];

    const int t = threadIdx.x;
    const int l = t & 31;
    const int w = t >> 5;              // 0..3
    const int s = blockIdx.x;          // sample
    const int m0 = s * 24;             // first global row

    // ---- A tile load (bf16, swizzled) + fused node_feats copy ----
    float4* out4 = (float4*)(out + OFF_NODE);
#pragma unroll
    for (int it = 0; it < 12; ++it) {
        int idx = it * 128 + t;              // 0..1535
        int r = idx >> 6, c4 = idx & 63;     // row 0..23
        const float4* src = (r < 8) ? text : ((r < 16) ? audio : facial);
        float4 v = src[((size_t)s * 8 + (r & 7)) * 64 + c4];
        stcs4(out4 + (size_t)(m0 + r) * 64 + c4, v);
        __nv_bfloat162 h0 = __float22bfloat162_rn(make_float2(v.x, v.y));
        __nv_bfloat162 h1 = __float22bfloat162_rn(make_float2(v.z, v.w));
        uint2 u;
        u.x = *reinterpret_cast<uint32_t*>(&h0);
        u.y = *reinterpret_cast<uint32_t*>(&h1);
        int off = (r * 512 + c4 * 8) ^ ((r & 7) << 4);
        *reinterpret_cast<uint2*>(smc + off) = u;
    }

    // ---- independent outputs (overlap other CTAs' MMA) ----
    {   // temporal attrs, vectorized: 42 edges * 4 float4
        const float4* emb4 = (const float4*)emb;
#pragma unroll
        for (int it = 0; it < 2; ++it) {
            int o = it * 128 + t;
            if (o < 168) {
                int e = o >> 2, quad = o & 3;
                int m = e / 14;
                float4 v4;
                if (quad < 2)       v4 = emb4[m * 2 + quad];
                else if (quad == 2) v4 = make_float4(0.0f, 0.125f, 1.0f, m * 0.25f);
                else                v4 = make_float4(0.0f, 0.0f, 0.0f, 0.0f);
                ((float4*)(out + OFF_EA))[(size_t)(s * E_PER + e) * 4 + quad] = v4;
            }
        }
    }
    if (t < 90) {                               // edge_index
        int e = t;
        int src, dst;
        if (e < 42) {
            int m = e / 14, r = e % 14, i = r >> 1, d = r & 1;
            int u_ = m * 8 + i, v_ = u_ + 1;
            src = d ? v_ : u_;
            dst = d ? u_ : v_;
        } else {
            int e2 = e - 42;
            int P = e2 >> 4, r = e2 & 15, i = r >> 1, d = r & 1;
            int oa = (P == 2) ? 8 : 0;
            int ob = (P == 0) ? 8 : 16;
            int a_ = oa + i, b_ = ob + i;
            src = d ? b_ : a_;
            dst = d ? a_ : b_;
        }
        out[OFF_EI + s * E_PER + e]           = (float)(src + s * P3);
        out[OFF_EI + EI_HALF + s * E_PER + e] = (float)(dst + s * P3);
    }
    if (t >= 96 && t < 120)                     // batch_vec: 24
        out[OFF_BV + m0 + (t - 96)] = (float)s;

    __syncthreads();   // A tile ready

    // ---- HMMA: warp w -> cols [64w, 64w+64), one 16-row m-tile ----
    const int rb = (w < 2) ? 0 : 8;             // q rows vs k rows
    const int SX = (l & 7) << 4;
    const uint32_t As_u = smem_u32(smc);
    const uint32_t a_base = As_u + (uint32_t)((rb + (l & 15)) * 512 + (l >> 4) * 16);

    const int g_ = l >> 2;
    const int tig = l & 3;
    const int SY = g_ << 4;

    // B frag pointer: c-groups 4w..4w+3 at +0, +512, +1024, +1536 uint4s
    const uint4* bp = g_Wfrag + (size_t)w * 2048 + l;

    float acc[8][4];
#pragma unroll
    for (int nt = 0; nt < 8; ++nt)
#pragma unroll
        for (int j = 0; j < 4; ++j) acc[nt][j] = 0.0f;

#pragma unroll
    for (int ks = 0; ks < 16; ++ks) {
        const uint32_t d0 = (uint32_t)(ks * 32);
        uint4 bf0 = __ldg(bp + d0);
        uint4 bf1 = __ldg(bp + d0 + 512);
        uint32_t a0, a1, a2, a3;
        LDSM_X4(a0, a1, a2, a3, (a_base + d0) ^ (uint32_t)SX);
        mma16816(acc[0], a0, a1, a2, a3, bf0.x, bf0.y);
        mma16816(acc[1], a0, a1, a2, a3, bf0.z, bf0.w);
        mma16816(acc[2], a0, a1, a2, a3, bf1.x, bf1.y);
        mma16816(acc[3], a0, a1, a2, a3, bf1.z, bf1.w);
        uint4 bf2 = __ldg(bp + d0 + 1024);
        uint4 bf3 = __ldg(bp + d0 + 1536);
        mma16816(acc[4], a0, a1, a2, a3, bf2.x, bf2.y);
        mma16816(acc[5], a0, a1, a2, a3, bf2.z, bf2.w);
        mma16816(acc[6], a0, a1, a2, a3, bf3.x, bf3.y);
        mma16816(acc[7], a0, a1, a2, a3, bf3.z, bf3.w);
    }

    __syncthreads();   // all warps done reading A before Y overlay

    // ---- bias + bf16 pack -> Y smem (overlays A) ----
    {
        const float* bias = (w < 2) ? bq : bk;
        const int mrow = rb + g_;
#pragma unroll
        for (int nt = 0; nt < 8; ++nt) {
            int gc = w * 64 + nt * 8 + tig * 2;          // global col 0..255
            int bidx = gc & 127;
            float b0 = __ldg(bias + bidx), b1 = __ldg(bias + bidx + 1);
            __nv_bfloat162 h0 = __float22bfloat162_rn(
                make_float2(acc[nt][0] + b0, acc[nt][1] + b1));
            __nv_bfloat162 h1 = __float22bfloat162_rn(
                make_float2(acc[nt][2] + b0, acc[nt][3] + b1));
            *reinterpret_cast<uint32_t*>(
                smc + ((mrow * 512 + gc * 2) ^ SY)) =
                *reinterpret_cast<uint32_t*>(&h0);
            *reinterpret_cast<uint32_t*>(
                smc + (((mrow + 8) * 512 + gc * 2) ^ SY)) =
                *reinterpret_cast<uint32_t*>(&h1);
        }
    }
    __syncthreads();   // Y ready

    // ---- dots + cross attrs: 2 pairs per iter, 16 lanes per pair ----
    const int h = l & 15;            // lane within pair group
#pragma unroll
    for (int j = 0; j < 3; ++j) {
        int p = w * 6 + j * 2 + (l >> 4);     // pair index 0..23
        int P = p >> 3, i = p & 7;
        int qrow = (P < 2) ? i : (8 + i);
        int krow = (P == 0) ? (8 + i) : (16 + i);
        uint4 qu = *reinterpret_cast<const uint4*>(
            smc + ((qrow * 512 + h * 16) ^ ((qrow & 7) << 4)));
        uint4 ku = *reinterpret_cast<const uint4*>(
            smc + ((krow * 512 + 256 + h * 16) ^ ((krow & 7) << 4)));
        float2 q0 = __bfloat1622float2(*reinterpret_cast<__nv_bfloat162*>(&qu.x));
        float2 q1 = __bfloat1622float2(*reinterpret_cast<__nv_bfloat162*>(&qu.y));
        float2 q2 = __bfloat1622float2(*reinterpret_cast<__nv_bfloat162*>(&qu.z));
        float2 q3 = __bfloat1622float2(*reinterpret_cast<__nv_bfloat162*>(&qu.w));
        float2 k0 = __bfloat1622float2(*reinterpret_cast<__nv_bfloat162*>(&ku.x));
        float2 k1 = __bfloat1622float2(*reinterpret_cast<__nv_bfloat162*>(&ku.y));
        float2 k2 = __bfloat1622float2(*reinterpret_cast<__nv_bfloat162*>(&ku.z));
        float2 k3 = __bfloat1622float2(*reinterpret_cast<__nv_bfloat162*>(&ku.w));
        float sqk = q0.x*k0.x + q0.y*k0.y + q1.x*k1.x + q1.y*k1.y
                  + q2.x*k2.x + q2.y*k2.y + q3.x*k3.x + q3.y*k3.y;
        float sqq = q0.x*q0.x + q0.y*q0.y + q1.x*q1.x + q1.y*q1.y
                  + q2.x*q2.x + q2.y*q2.y + q3.x*q3.x + q3.y*q3.y;
        float skk = k0.x*k0.x + k0.y*k0.y + k1.x*k1.x + k1.y*k1.y
                  + k2.x*k2.x + k2.y*k2.y + k3.x*k3.x + k3.y*k3.y;
#pragma unroll
        for (int off = 8; off > 0; off >>= 1) {
            sqk += __shfl_xor_sync(0xffffffffu, sqk, off);
            sqq += __shfl_xor_sync(0xffffffffu, sqq, off);
            skk += __shfl_xor_sync(0xffffffffu, skk, off);
        }
        float dv = sqk * rsqrtf(fmaxf(sqq, 1e-24f)) * rsqrtf(fmaxf(skk, 1e-24f));
        float disc = 1.0f / (1.0f + __expf(dv));
        int et = (disc > 0.4f) ? 4 : 3;
        float v;
        if (h < 8)        v = emb[et * 8 + h];
        else if (h == 8)  v = disc;
        else if (h == 11) v = et * 0.25f;
        else              v = 0.0f;
        float* base = out + OFF_EA
            + (size_t)(s * E_PER + 42 + 2 * p) * EDGE_DIM;
        base[h]      = v;
        base[h + 16] = v;
    }
}

// ---------------------------------------------------------------------------
extern "C" void kernel_launch(void* const* d_in, const int* in_sizes, int n_in,
                              void* d_out, int out_size)
{
    const float* z_text   = (const float*)d_in[0];
    const float* z_audio  = (const float*)d_in[1];
    const float* z_facial = (const float*)d_in[2];
    const float* Wq       = (const float*)d_in[3];
    const float* bq       = (const float*)d_in[4];
    const float* Wk       = (const float*)d_in[5];
    const float* bk       = (const float*)d_in[6];
    const float* emb      = (const float*)d_in[7];
    float* out = (float*)d_out;

    cudaFuncSetAttribute(fused_kernel, cudaFuncAttributeMaxDynamicSharedMemorySize,
                         FS_TOTAL);

    prep_kernel<<<32, 256>>>(Wq, Wk);

    fused_kernel<<<BB, 128, FS_TOTAL>>>(
        (const float4*)z_text, (const float4*)z_audio, (const float4*)z_facial,
        bq, bk, emb, out);
}